// round 17
// baseline (speedup 1.0000x reference)
#include <cuda_runtime.h>
#include <math.h>

// ---------------------------------------------------------------------------
// GRU T=512 B=64 IC=HC=512 L=2 — fused persistent kernel, v3.
//
// 128 CTAs x 256 threads. CTAs 0..63 = layer 1, 64..127 = layer 2.
// Each CTA owns 16 gate cols (8 r + 8 z) and 8 g cols; full 1024-wide (x||h)
// weight rows SMEM-resident as f32x2 pairs (input GEMMs absorbed).
//
// Sync: NO global atomic barrier. Per-CTA generation flags:
//   g_fA[c] = steps whose phase A this CTA finished, g_fB[c] likewise.
//   Phase A of step t waits: own-layer fB >= t (all 64); layer 2 additionally
//   waits layer-1 fB >= t+1 (h1T[t] ready). Phase B waits own-layer fA >= t+1.
//   64(/128) threads poll 64(/128) DISTINCT flag addresses in parallel.
//   Layer 1 never waits on layer 2 (layers decoupled).
//
// Per step: dot A (x-warps: 8 WA + 4 WB-x accs; h-warps: 8 WA accs),
// combine A (r,z; r*h -> L2 buffer; z -> smem), flagA+wait, dot B (r*h only),
// combine B (g, h update; x-part of pre2 comes from smem xred). h register-
// resident in its combine thread. All math FFMA2 (fma.rn.f32x2).
// ---------------------------------------------------------------------------

#define TSTEPS 512
#define BATCH  64
#define HC     512
#define NCTA   128
#define NTHR   256
#define RSTR   264   // padded reduction stride (ull)

#define FFMA2(d, a, b) \
    asm("fma.rn.f32x2 %0, %1, %2, %0;" : "+l"(d) : "l"(a), "l"(b))
#define PACK2(d, lo, hi) \
    asm("mov.b64 %0, {%1, %2};" : "=l"(d) : "r"(__float_as_uint(lo)), "r"(__float_as_uint(hi)))
#define UNPACK2(lo, hi, s) do { unsigned _ulo, _uhi; \
    asm("mov.b64 {%0, %1}, %2;" : "=r"(_ulo), "=r"(_uhi) : "l"(s)); \
    lo = __uint_as_float(_ulo); hi = __uint_as_float(_uhi); } while (0)

typedef unsigned long long ull;

// Packed streaming layouts: [k4][b][s] (one float4 per (k4,b))
__device__ float g_xT [TSTEPS * BATCH * HC];
__device__ float g_h1T[TSTEPS * BATCH * HC];
__device__ float g_hT [2 * BATCH * HC];
__device__ float g_rhT[2 * BATCH * HC];
__device__ volatile unsigned g_fA[NCTA];
__device__ volatile unsigned g_fB[NCTA];

// Prep: transpose x into packed layout, broadcast h0, zero flags.
__global__ __launch_bounds__(256) void prep_kernel(const float* __restrict__ x,
                                                   const float* __restrict__ hid)
{
    const size_t o = (size_t)blockIdx.x * 256 + threadIdx.x;
    const int s  = (int)(o & 3);
    const int b  = (int)((o >> 2) & 63);
    const int k4 = (int)((o >> 8) & 127);
    const size_t t = o >> 15;
    g_xT[o] = x[(t * 64 + b) * 512 + k4 * 4 + s];
    if (o < 2 * 32768) {
        const int l = (int)(o >> 15);
        g_hT[o] = hid[l * 512 + k4 * 4 + s];
    }
    if (o < NCTA) { g_fA[o] = 0u; g_fB[o] = 0u; }
}

__global__ __launch_bounds__(NTHR, 1) void gru_fused(
    const float* __restrict__ W1, const float* __restrict__ W2,
    const float* __restrict__ bias1, const float* __restrict__ bias2,
    const float* __restrict__ hid,
    float* __restrict__ out_seq, float* __restrict__ out_hs)
{
    extern __shared__ ull smem[];
    ull* WAp  = smem;                  // [k<1024][jp<8] : 8192 ull = 64 KB
    ull* WBp  = WAp + 8192;            // [k<1024][jp<4] : 4096 ull = 32 KB
    ull* red  = WBp + 4096;            // [jp<8][RSTR]   : 16.9 KB
    ull* xred = red + 8 * RSTR;        // [jp<4][RSTR]   :  8.4 KB
    float* zbuf = (float*)(xred + 4 * RSTR);   // [64][8] : 2 KB

    const int c = blockIdx.x, tid = threadIdx.x;
    const int layer = c >> 6, cl = c & 63;
    const int w = tid >> 5, lane = tid & 31;
    const int kq = w >> 1, bh = w & 1;   // k-quarter, batch-half
    const int b = bh * 32 + lane;

    const float* W1L = W1 + (size_t)layer * 1024 * 1024;
    const float* W2L = W2 + (size_t)layer * 512 * 1024;

    // Pack weights: WAp jp<4 = r col pairs, jp>=4 = z col pairs; WBp = g pairs.
    for (int i = tid; i < 8192; i += NTHR) {
        const int jp = i >> 10, k = i & 1023;
        const int jr = (jp < 4) ? (cl * 8 + 2 * jp) : (512 + cl * 8 + 2 * (jp - 4));
        ull u;
        PACK2(u, W1L[(size_t)jr * 1024 + k], W1L[(size_t)(jr + 1) * 1024 + k]);
        WAp[(size_t)k * 8 + jp] = u;
    }
    for (int i = tid; i < 4096; i += NTHR) {
        const int jp = i >> 10, k = i & 1023;
        const int jr = cl * 8 + 2 * jp;
        ull u;
        PACK2(u, W2L[(size_t)jr * 1024 + k], W2L[(size_t)(jr + 1) * 1024 + k]);
        WBp[(size_t)k * 4 + jp] = u;
    }

    // Combine-thread mapping: b2 = batch, q = pair index (r-pair q, z-pair q,
    // g-pair q all owned by this thread; h register-resident).
    const int b2 = tid >> 2, q = tid & 3;
    const int j0 = cl * 8 + 2 * q;
    const float bR0 = bias1[(size_t)layer * 1024 + j0];
    const float bR1 = bias1[(size_t)layer * 1024 + j0 + 1];
    const float bZ0 = bias1[(size_t)layer * 1024 + 512 + j0];
    const float bZ1 = bias1[(size_t)layer * 1024 + 512 + j0 + 1];
    const float bG0 = bias2[(size_t)layer * 512 + j0];
    const float bG1 = bias2[(size_t)layer * 512 + j0 + 1];
    float h0r = hid[layer * 512 + j0];
    float h1r = hid[layer * 512 + j0 + 1];

    float* hTl  = g_hT  + (size_t)layer * 32768;
    float* rhTl = g_rhT + (size_t)layer * 32768;
    const float4* hT4  = (const float4*)hTl;
    const float4* rhT4 = (const float4*)rhTl;
    const int bh2 = b2 >> 5, bl = b2 & 31;

    __syncthreads();

    for (int t = 0; t < TSTEPS; t++) {
        const float4* xsrc = (const float4*)((layer ? g_h1T : g_xT) + (size_t)t * 32768);

        // -------- wait for phase-A dependencies --------
        if (layer == 0) {
            if (tid < 64) { while (g_fB[tid] < (unsigned)t) { } }
        } else {
            if (tid < 64)       { while (g_fB[64 + tid] < (unsigned)t) { } }
            else if (tid < 128) { while (g_fB[tid - 64] < (unsigned)(t + 1)) { } }
        }
        __syncthreads();
        __threadfence();

        // -------- dot A --------
        if (kq < 2) {
            // x-warp: 64 k4 of x, 8 WA accs + 4 WB-x accs
            ull acc[12];
            #pragma unroll
            for (int p = 0; p < 12; p++) acc[p] = 0ull;
            const float4* sp = xsrc + (size_t)(kq * 64) * 64 + b;
            float4 buf[4];
            #pragma unroll
            for (int d = 0; d < 4; d++) buf[d] = __ldcg(sp + (size_t)d * 64);
            #pragma unroll 2
            for (int ib = 0; ib < 16; ib++) {
                #pragma unroll
                for (int u = 0; u < 4; u++) {
                    const int i = ib * 4 + u;
                    const float4 v = buf[u];
                    if (i + 4 < 64) buf[u] = __ldcg(sp + (size_t)(i + 4) * 64);
                    const float vs[4] = {v.x, v.y, v.z, v.w};
                    #pragma unroll
                    for (int s = 0; s < 4; s++) {
                        const int k = (kq * 64 + i) * 4 + s;
                        ull vd; PACK2(vd, vs[s], vs[s]);
                        const ulonglong2* wa = (const ulonglong2*)&WAp[(size_t)k * 8];
                        const ulonglong2* wb = (const ulonglong2*)&WBp[(size_t)k * 4];
                        const ulonglong2 a0 = wa[0], a1 = wa[1], a2 = wa[2], a3 = wa[3];
                        const ulonglong2 c0 = wb[0], c1 = wb[1];
                        FFMA2(acc[0], vd, a0.x);  FFMA2(acc[1], vd, a0.y);
                        FFMA2(acc[2], vd, a1.x);  FFMA2(acc[3], vd, a1.y);
                        FFMA2(acc[4], vd, a2.x);  FFMA2(acc[5], vd, a2.y);
                        FFMA2(acc[6], vd, a3.x);  FFMA2(acc[7], vd, a3.y);
                        FFMA2(acc[8], vd, c0.x);  FFMA2(acc[9], vd, c0.y);
                        FFMA2(acc[10], vd, c1.x); FFMA2(acc[11], vd, c1.y);
                    }
                }
            }
            #pragma unroll
            for (int jp = 0; jp < 8; jp++) red[jp * RSTR + tid] = acc[jp];
            #pragma unroll
            for (int jp = 0; jp < 4; jp++) xred[jp * RSTR + tid] = acc[8 + jp];
        } else {
            // h-warp: 64 k4 of h, 8 WA accs
            ull acc[8];
            #pragma unroll
            for (int p = 0; p < 8; p++) acc[p] = 0ull;
            const float4* sp = hT4 + (size_t)((kq - 2) * 64) * 64 + b;
            float4 buf[4];
            #pragma unroll
            for (int d = 0; d < 4; d++) buf[d] = __ldcg(sp + (size_t)d * 64);
            #pragma unroll 2
            for (int ib = 0; ib < 16; ib++) {
                #pragma unroll
                for (int u = 0; u < 4; u++) {
                    const int i = ib * 4 + u;
                    const float4 v = buf[u];
                    if (i + 4 < 64) buf[u] = __ldcg(sp + (size_t)(i + 4) * 64);
                    const float vs[4] = {v.x, v.y, v.z, v.w};
                    #pragma unroll
                    for (int s = 0; s < 4; s++) {
                        const int k = 512 + ((kq - 2) * 64 + i) * 4 + s;
                        ull vd; PACK2(vd, vs[s], vs[s]);
                        const ulonglong2* wa = (const ulonglong2*)&WAp[(size_t)k * 8];
                        const ulonglong2 a0 = wa[0], a1 = wa[1], a2 = wa[2], a3 = wa[3];
                        FFMA2(acc[0], vd, a0.x); FFMA2(acc[1], vd, a0.y);
                        FFMA2(acc[2], vd, a1.x); FFMA2(acc[3], vd, a1.y);
                        FFMA2(acc[4], vd, a2.x); FFMA2(acc[5], vd, a2.y);
                        FFMA2(acc[6], vd, a3.x); FFMA2(acc[7], vd, a3.y);
                    }
                }
            }
            #pragma unroll
            for (int jp = 0; jp < 8; jp++) red[jp * RSTR + tid] = acc[jp];
        }
        __syncthreads();

        // -------- combine A: r, z --------
        {
            float sr0 = 0.f, sr1 = 0.f, sz0 = 0.f, sz1 = 0.f;
            #pragma unroll
            for (int kk = 0; kk < 4; kk++) {
                const int slot = (kk * 2 + bh2) * 32 + bl;
                float lo, hi;
                UNPACK2(lo, hi, red[q * RSTR + slot]);       sr0 += lo; sr1 += hi;
                UNPACK2(lo, hi, red[(q + 4) * RSTR + slot]); sz0 += lo; sz1 += hi;
            }
            const float r0 = 1.f / (1.f + __expf(-(sr0 + bR0)));
            const float r1 = 1.f / (1.f + __expf(-(sr1 + bR1)));
            const float z0 = 1.f / (1.f + __expf(-(sz0 + bZ0)));
            const float z1 = 1.f / (1.f + __expf(-(sz1 + bZ1)));
            zbuf[b2 * 8 + 2 * q]     = z0;
            zbuf[b2 * 8 + 2 * q + 1] = z1;
            float2 rh; rh.x = r0 * h0r; rh.y = r1 * h1r;
            *(float2*)&rhTl[((j0 >> 2) * 64 + b2) * 4 + (j0 & 3)] = rh;
        }
        __syncthreads();

        // -------- publish phase A, wait own-layer phase A --------
        if (tid == 0) { __threadfence(); g_fA[c] = (unsigned)(t + 1); }
        if (tid < 64) { while (g_fA[layer * 64 + tid] < (unsigned)(t + 1)) { } }
        __syncthreads();
        __threadfence();

        // -------- dot B: r*h only (x-part already in xred) --------
        {
            ull acc[4];
            #pragma unroll
            for (int p = 0; p < 4; p++) acc[p] = 0ull;
            const float4* sp = rhT4 + (size_t)(kq * 32) * 64 + b;
            float4 buf[4];
            #pragma unroll
            for (int d = 0; d < 4; d++) buf[d] = __ldcg(sp + (size_t)d * 64);
            #pragma unroll 2
            for (int ib = 0; ib < 8; ib++) {
                #pragma unroll
                for (int u = 0; u < 4; u++) {
                    const int i = ib * 4 + u;
                    const float4 v = buf[u];
                    if (i + 4 < 32) buf[u] = __ldcg(sp + (size_t)(i + 4) * 64);
                    const float vs[4] = {v.x, v.y, v.z, v.w};
                    #pragma unroll
                    for (int s = 0; s < 4; s++) {
                        const int k = 512 + (kq * 32 + i) * 4 + s;
                        ull vd; PACK2(vd, vs[s], vs[s]);
                        const ulonglong2* wb = (const ulonglong2*)&WBp[(size_t)k * 4];
                        const ulonglong2 c0 = wb[0], c1 = wb[1];
                        FFMA2(acc[0], vd, c0.x); FFMA2(acc[1], vd, c0.y);
                        FFMA2(acc[2], vd, c1.x); FFMA2(acc[3], vd, c1.y);
                    }
                }
            }
            #pragma unroll
            for (int jp = 0; jp < 4; jp++) red[jp * RSTR + tid] = acc[jp];
        }
        __syncthreads();

        // -------- combine B: g, h update --------
        {
            float s0 = 0.f, s1 = 0.f;
            #pragma unroll
            for (int kk = 0; kk < 4; kk++) {     // r*h partials
                const int slot = (kk * 2 + bh2) * 32 + bl;
                float lo, hi;
                UNPACK2(lo, hi, red[q * RSTR + slot]);
                s0 += lo; s1 += hi;
            }
            #pragma unroll
            for (int kk = 0; kk < 2; kk++) {     // x-part partials (phase A)
                const int slot = (kk * 2 + bh2) * 32 + bl;
                float lo, hi;
                UNPACK2(lo, hi, xred[q * RSTR + slot]);
                s0 += lo; s1 += hi;
            }
            const float g0 = tanhf(s0 + bG0);
            const float g1 = tanhf(s1 + bG1);
            const float z0 = zbuf[b2 * 8 + 2 * q];
            const float z1 = zbuf[b2 * 8 + 2 * q + 1];
            const float hn0 = z0 * h0r + (1.f - z0) * g0;
            const float hn1 = z1 * h1r + (1.f - z1) * g1;
            h0r = hn0; h1r = hn1;
            float2 hv; hv.x = hn0; hv.y = hn1;
            *(float2*)&hTl[((j0 >> 2) * 64 + b2) * 4 + (j0 & 3)] = hv;
            if (layer == 0)
                *(float2*)&g_h1T[((size_t)t * 128 + (j0 >> 2)) * 256 + b2 * 4 + (j0 & 3)] = hv;
            else
                *(float2*)&out_seq[((size_t)t * 64 + b2) * 512 + j0] = hv;
            if (t == TSTEPS - 1)
                *(float2*)&out_hs[(size_t)layer * 32768 + b2 * 512 + j0] = hv;
        }
        __syncthreads();

        // -------- publish phase B --------
        if (tid == 0) { __threadfence(); g_fB[c] = (unsigned)(t + 1); }
    }
}

// ---------------------------------------------------------------------------
// Inputs: x[512,64,512], hiddens[2,1,512], W1[2,1024,1024], b1[2,1024],
//         W2[2,512,1024], b2[2,512]
// Output: out_seq[512,64,512] ++ hs[2,64,512]
// ---------------------------------------------------------------------------
extern "C" void kernel_launch(void* const* d_in, const int* in_sizes, int n_in,
                              void* d_out, int out_size)
{
    const float* x   = (const float*)d_in[0];
    const float* hid = (const float*)d_in[1];
    const float* W1  = (const float*)d_in[2];
    const float* b1  = (const float*)d_in[3];
    const float* W2  = (const float*)d_in[4];
    const float* b2  = (const float*)d_in[5];

    float* out_seq = (float*)d_out;
    float* out_hs  = (float*)d_out + (size_t)TSTEPS * BATCH * HC;

    const int SMEM_BYTES = (8192 + 4096 + 12 * RSTR) * 8 + 2048;  // ~125 KB
    cudaFuncSetAttribute(gru_fused, cudaFuncAttributeMaxDynamicSharedMemorySize,
                         SMEM_BYTES);

    prep_kernel<<<(TSTEPS * BATCH * HC) / 256, 256>>>(x, hid);
    gru_fused<<<NCTA, NTHR, SMEM_BYTES>>>(W1, W2, b1, b2, hid, out_seq, out_hs);
}